// round 11
// baseline (speedup 1.0000x reference)
#include <cuda_runtime.h>
#include <cuda_bf16.h>
#include <cstdint>

// CIF: continuous integrate-and-fire. B=32, T=2000, H=512, L=256, thresh=0.95
//
// Scan (32 CTAs x 256 threads, one per row): dp row sum -> scale; serial fp32
// chain (bit-exact vs reference) in 8 groups of 256 steps; after each group,
// helper threads replay bit-exactly, emit fire records (fpos/rem/cur) to
// global, and thread 0 RELEASES a per-row progress counter.
// Gather (grid (B,L) x 128, PDL-overlapped): each CTA acquires progress[b]
// until its token is published, then does the segmented weighted gather:
//   out[b,k,:] = rem[k-1]*h[fpos[k-1]] + sum alphas[t]*scale * h[t] + cur[k]*h[fpos[k]]
// Overlap: gather kernel launched with programmatic stream serialization; scan
// resets progress and triggers early so the BW-bound gather runs underneath
// the latency-bound scan.

#define CIF_B 32
#define CIF_T 2000
#define CIF_H 512
#define CIF_L 256
#define CIF_THRESH 0.95f

#define CHUNK 32
#define CH_PER_G 8
#define NGROUP 8
#define NCHUNK (CH_PER_G * NGROUP)        // 64
#define T_PAD (NCHUNK * CHUNK)            // 2048 >= 2000 (zero padded)

#define DONE_BIT (1 << 30)
#define CNT_MASK (DONE_BIT - 1)

// Scratch (allocation-free contract; zero-initialized at module load)
__device__ int   g_fpos[CIF_B * CIF_L];
__device__ float g_rem [CIF_B * CIF_L];
__device__ float g_cur [CIF_B * CIF_L];
__device__ float g_scale[CIF_B];
__device__ int   g_prog[CIF_B];           // published token count | DONE_BIT

__device__ __forceinline__ void st_release_gpu(int* p, int v)
{
    asm volatile("st.release.gpu.s32 [%0], %1;" :: "l"(p), "r"(v) : "memory");
}
__device__ __forceinline__ int ld_acquire_gpu(const int* p)
{
    int v;
    asm volatile("ld.acquire.gpu.s32 %0, [%1];" : "=r"(v) : "l"(p) : "memory");
    return v;
}

// minimal CIF step: FADD -> FSETP -> FSEL (pred-as-data)
__device__ __forceinline__ void cif_step_min(float a, float& integ)
{
    float i2, sub;
    asm("{\n\t"
        ".reg .pred p;\n\t"
        "add.f32 %0, %2, %3;\n\t"               // i2 = integ + a
        "setp.ge.f32 p, %0, 0f3F733333;\n\t"    // fire = i2 >= 0.95f
        "add.f32 %1, %0, 0fBF800000;\n\t"       // sub = i2 - 1.0f (Sterbenz-exact)
        "selp.f32 %2, %1, %0, p;\n\t"           // integ = fire ? sub : i2
        "}"
        : "=f"(i2), "=f"(sub), "+f"(integ)
        : "f"(a));
}

// ---------------------------------------------------------------------------
// Kernel A: rescale + group-pipelined serial scan with progressive publish
// ---------------------------------------------------------------------------
__global__ __launch_bounds__(256, 1)
void cif_scan_kernel(const float* __restrict__ alphas,
                     const int* __restrict__ target_lengths)
{
    __shared__ __align__(16) float s_a[T_PAD];
    __shared__ float  s_i0g[CH_PER_G];       // chunk-start integ within group
    __shared__ int    s_cntg[CH_PER_G];      // fires per chunk within group
    __shared__ int    s_offg[CH_PER_G + 1];  // token offsets within group
    __shared__ double s_red[256];
    __shared__ float  s_scale;

    const int b   = blockIdx.x;
    const int tid = threadIdx.x;
    const float* arow = alphas + b * CIF_T;

    // reset progress for this launch, then release the dependent gather launch
    if (tid == 0)
        g_prog[b] = 0;
    cudaTriggerProgrammaticLaunchCompletion();

    // --- deterministic double-precision row sum ---
    double acc = 0.0;
    for (int t = tid; t < CIF_T; t += 256)
        acc += (double)arow[t];
    s_red[tid] = acc;
    __syncthreads();
    for (int off = 128; off > 0; off >>= 1) {
        if (tid < off) s_red[tid] += s_red[tid + off];
        __syncthreads();
    }
    if (tid == 0) {
        float sc = (float)target_lengths[b] / (float)s_red[0];
        s_scale = sc;
        g_scale[b] = sc;
    }
    __syncthreads();

    // --- stage scaled alphas (fp32 mul, like reference); zero pad ---
    const float scale = s_scale;
    for (int t = tid; t < T_PAD; t += 256)
        s_a[t] = (t < CIF_T) ? arow[t] * scale : 0.0f;
    __syncthreads();

    // --- group-pipelined scan: serial chain -> replay -> emit -> publish ---
    float integ = 0.0f;       // serial state (thread 0)
    int   goff  = 0;          // tokens before this group (thread 0)

    for (int g = 0; g < NGROUP; ++g) {
        // (1) serial chain over this group's 8 chunks (256 steps), thread 0
        if (tid == 0) {
            #pragma unroll 1
            for (int c = 0; c < CH_PER_G; ++c) {
                s_i0g[c] = integ;
                const float4* a4 = reinterpret_cast<const float4*>(
                    s_a + (g * CH_PER_G + c) * CHUNK);
                float4 v[CHUNK / 4];
                #pragma unroll
                for (int q = 0; q < CHUNK / 4; ++q)
                    v[q] = a4[q];
                #pragma unroll
                for (int q = 0; q < CHUNK / 4; ++q) {
                    cif_step_min(v[q].x, integ);
                    cif_step_min(v[q].y, integ);
                    cif_step_min(v[q].z, integ);
                    cif_step_min(v[q].w, integ);
                }
            }
        }
        __syncthreads();

        // (2) replay pass 1: 8 threads count fires per chunk (bit-exact)
        if (tid < CH_PER_G) {
            float ii = s_i0g[tid];
            int cnt = 0;
            const int tbase = (g * CH_PER_G + tid) * CHUNK;
            #pragma unroll
            for (int j = 0; j < CHUNK; ++j) {
                float a    = s_a[tbase + j];
                float i2   = ii + a;
                bool  fire = (i2 >= CIF_THRESH);
                ii   = fire ? (i2 - 1.0f) : i2;
                cnt += fire ? 1 : 0;
            }
            s_cntg[tid] = cnt;
        }
        __syncthreads();

        // (3) prefix over the group's 8 chunks
        if (tid == 0) {
            int a0 = goff;
            #pragma unroll
            for (int c = 0; c < CH_PER_G; ++c) {
                s_offg[c] = a0;
                a0 += s_cntg[c];
            }
            s_offg[CH_PER_G] = a0;
        }
        __syncthreads();

        // (4) replay pass 2: emit records directly to global (bit-exact)
        if (tid < CH_PER_G) {
            float ii = s_i0g[tid];
            int   k  = s_offg[tid];
            const int tbase = (g * CH_PER_G + tid) * CHUNK;
            #pragma unroll
            for (int j = 0; j < CHUNK; ++j) {
                float a    = s_a[tbase + j];
                float i2   = ii + a;
                bool  fire = (i2 >= CIF_THRESH);
                float cur  = 1.0f - ii;           // dist_completion (old integ)
                if (fire) {
                    if (k < CIF_L) {
                        g_fpos[b * CIF_L + k] = tbase + j;
                        g_rem [b * CIF_L + k] = a - cur;   // remainds
                        g_cur [b * CIF_L + k] = cur;
                    }
                    k++;
                }
                ii = fire ? (i2 - 1.0f) : i2;
            }
            __threadfence();     // make this thread's record STGs GPU-visible
        }
        __syncthreads();

        // (5) publish progress (release)
        if (tid == 0) {
            goff = s_offg[CH_PER_G];
            int pub = goff < CIF_L ? goff : CIF_L;
            if (g == NGROUP - 1) pub |= DONE_BIT;
            st_release_gpu(&g_prog[b], pub);
        }
        __syncthreads();
    }
}

// ---------------------------------------------------------------------------
// Kernel B: PDL-overlapped segmented gather. grid (B, L) x 128 threads.
// blockIdx.x = batch row (fast -> wave order matches publish order),
// blockIdx.y = token.
// ---------------------------------------------------------------------------
__global__ __launch_bounds__(128, 12)
void cif_gather_kernel(const float* __restrict__ hidden,
                       const float* __restrict__ alphas,
                       float* __restrict__ out)
{
    cudaGridDependencySynchronize();   // scan's progress resets are visible

    const int b   = blockIdx.x;
    const int k   = blockIdx.y;
    const int tid = threadIdx.x;
    const int HS  = CIF_H / 4;

    // wait until token k of row b is published (or row done)
    int cnt;
    for (;;) {
        int p = ld_acquire_gpu(&g_prog[b]);
        cnt = p & CNT_MASK;
        if (cnt > k || (p & DONE_BIT)) break;
        __nanosleep(256);
    }

    float4* out4 = reinterpret_cast<float4*>(out + ((size_t)(b * CIF_L + k)) * CIF_H) + tid;

    if (k >= cnt) {                    // row done and k >= nf
        *out4 = make_float4(0.f, 0.f, 0.f, 0.f);
        return;
    }

    const float   scale = g_scale[b];
    const int     te    = g_fpos[b * CIF_L + k];
    const float*  arow  = alphas + b * CIF_T;
    const float4* h4    = reinterpret_cast<const float4*>(hidden + (size_t)b * CIF_T * CIF_H) + tid;

    float4 accv;
    int t0;
    if (k == 0) {
        t0 = 0;
        accv = make_float4(0.f, 0.f, 0.f, 0.f);
    } else {
        const int   ts = g_fpos[b * CIF_L + k - 1];
        const float wt = g_rem[b * CIF_L + k - 1];
        float4 hv = __ldg(h4 + (size_t)ts * HS);
        accv = make_float4(wt * hv.x, wt * hv.y, wt * hv.z, wt * hv.w);
        t0 = ts + 1;
    }

    // interior frames: weight = alphas[t]*scale (bit-identical to scan's a)
    int t = t0;
    for (; t + 4 <= te; t += 4) {
        float w0 = __ldg(arow + t)     * scale;
        float w1 = __ldg(arow + t + 1) * scale;
        float w2 = __ldg(arow + t + 2) * scale;
        float w3 = __ldg(arow + t + 3) * scale;
        float4 h0 = __ldg(h4 + (size_t)(t    ) * HS);
        float4 h1 = __ldg(h4 + (size_t)(t + 1) * HS);
        float4 h2 = __ldg(h4 + (size_t)(t + 2) * HS);
        float4 h3 = __ldg(h4 + (size_t)(t + 3) * HS);
        accv.x = fmaf(w0, h0.x, accv.x); accv.y = fmaf(w0, h0.y, accv.y);
        accv.z = fmaf(w0, h0.z, accv.z); accv.w = fmaf(w0, h0.w, accv.w);
        accv.x = fmaf(w1, h1.x, accv.x); accv.y = fmaf(w1, h1.y, accv.y);
        accv.z = fmaf(w1, h1.z, accv.z); accv.w = fmaf(w1, h1.w, accv.w);
        accv.x = fmaf(w2, h2.x, accv.x); accv.y = fmaf(w2, h2.y, accv.y);
        accv.z = fmaf(w2, h2.z, accv.z); accv.w = fmaf(w2, h2.w, accv.w);
        accv.x = fmaf(w3, h3.x, accv.x); accv.y = fmaf(w3, h3.y, accv.y);
        accv.z = fmaf(w3, h3.z, accv.z); accv.w = fmaf(w3, h3.w, accv.w);
    }
    for (; t < te; ++t) {
        float  w  = __ldg(arow + t) * scale;
        float4 hv = __ldg(h4 + (size_t)t * HS);
        accv.x = fmaf(w, hv.x, accv.x);
        accv.y = fmaf(w, hv.y, accv.y);
        accv.z = fmaf(w, hv.z, accv.z);
        accv.w = fmaf(w, hv.w, accv.w);
    }
    // segment-end fire frame: weight = cur
    {
        float  wc = g_cur[b * CIF_L + k];
        float4 hv = __ldg(h4 + (size_t)te * HS);
        accv.x = fmaf(wc, hv.x, accv.x);
        accv.y = fmaf(wc, hv.y, accv.y);
        accv.z = fmaf(wc, hv.z, accv.z);
        accv.w = fmaf(wc, hv.w, accv.w);
    }
    *out4 = accv;
}

// ---------------------------------------------------------------------------
extern "C" void kernel_launch(void* const* d_in, const int* in_sizes, int n_in,
                              void* d_out, int out_size)
{
    const float* hidden = (const float*)d_in[0];
    const float* alphas = (const float*)d_in[1];
    const int*   tlen   = (const int*)d_in[2];
    float* out = (float*)d_out;

    cif_scan_kernel<<<CIF_B, 256>>>(alphas, tlen);

    // gather overlaps the scan via programmatic dependent launch
    cudaLaunchConfig_t cfg = {};
    cfg.gridDim  = dim3(CIF_B, CIF_L, 1);
    cfg.blockDim = dim3(128, 1, 1);
    cudaLaunchAttribute attrs[1];
    attrs[0].id = cudaLaunchAttributeProgrammaticStreamSerialization;
    attrs[0].val.programmaticStreamSerializationAllowed = 1;
    cfg.attrs = attrs;
    cfg.numAttrs = 1;
    cudaLaunchKernelEx(&cfg, cif_gather_kernel, hidden, alphas, out);
}